// round 3
// baseline (speedup 1.0000x reference)
#include <cuda_runtime.h>

#define BB  256
#define TT  1024
#define NUM 126
#define L   128
#define THR 256

// monotone float -> uint key (order-preserving), and inverse
__device__ __forceinline__ unsigned fkey(float f) {
    int b = __float_as_int(f);
    return (unsigned)(b >= 0 ? (b ^ 0x80000000) : ~b);
}
__device__ __forceinline__ float finv(unsigned k) {
    int b = (k & 0x80000000u) ? (int)(k ^ 0x80000000u) : ~(int)k;
    return __int_as_float(b);
}

__global__ __launch_bounds__(THR) void crf_fwd_kernel(
    const float* __restrict__ logits,     // [B, T, NUM]
    const int*   __restrict__ labels,     // [B, T]
    const int*   __restrict__ lens,       // [B]
    const float* __restrict__ trans,      // [L, L]
    float*       __restrict__ out)        // [B]
{
    const int b    = blockIdx.x;
    const int tid  = threadIdx.x;
    const int j    = tid >> 1;           // state 0..127 (two threads per state)
    const int h    = tid & 1;            // half of the dot this thread owns
    const int warp = tid >> 5;
    const int lane = tid & 31;
    const int len  = lens[b];

    __shared__ __align__(16) float v[2][L];
    __shared__ __align__(16) float wmax[2][8];
    __shared__ float sred[8];

    // ---- E2[i] = packed f32x2 of exp(trans[j][64h + 2i .. +1]) ----
    unsigned long long E2[32];
    const float* trow = trans + j * L + (h << 6);
    #pragma unroll
    for (int i = 0; i < 32; ++i) {
        float lo = __expf(trow[2 * i]);
        float hi = __expf(trow[2 * i + 1]);
        asm("mov.b64 %0, {%1, %2};" : "=l"(E2[i]) : "f"(lo), "f"(hi));
    }

    // ---- gold score (cooperative over time) ----
    const int*   lab_b = labels + b * TT;
    const float* log_b = logits + (size_t)b * TT * NUM;

    float g = 0.f;
    for (int t = tid; t < len; t += THR) {
        int lab = lab_b[t];
        g += log_b[(size_t)t * NUM + lab];               // unary
        if (t > 0) g += trans[lab * L + lab_b[t - 1]];   // binary
    }
    if (tid == 0) {
        g += trans[lab_b[0] * L + (L - 2)];              // start -> labels[0]
        g += trans[(L - 1) * L + lab_b[len - 1]];        // labels[len-1] -> end
    }
    #pragma unroll
    for (int o = 16; o; o >>= 1) g += __shfl_xor_sync(0xffffffffu, g, o);
    if (lane == 0) sred[warp] = g;
    __syncthreads();
    float gold = 0.f;
    #pragma unroll
    for (int w = 0; w < 8; ++w) gold += sred[w];

    // ---- forward recursion (alpha replicated in both lanes of a pair) ----
    float alpha = (j == L - 2) ? 0.f : -100.f;
    float m_lag = 0.f;                               // exact max of alpha0
    float lg_cur = (j < NUM) ? log_b[j] : -1000.f;
    float lg_n1  = (j < NUM && 1 < len) ? log_b[NUM + j] : -1000.f;

    int p = 0;
    for (int t = 0; t < len; ++t) {
        // prefetch 2 steps ahead (hides ~577cyc DRAM latency over 2 steps)
        float lg_n2 = -1000.f;
        if (j < NUM && t + 2 < len)
            lg_n2 = log_b[(size_t)(t + 2) * NUM + j];

        // per-warp max of entering alpha -> smem (consumed NEXT step; off path)
        float mw = finv(__reduce_max_sync(0xffffffffu, fkey(alpha)));
        if (lane == 0) wmax[p][warp] = mw;

        if (h == 0) v[p][j] = __expf(alpha - m_lag);   // lagged shift: exact alg.
        __syncthreads();                               // ONE barrier / step

        // global max for next step's shift (overlaps the dot; not on chain)
        float4 w0 = ((const float4*)wmax[p])[0];
        float4 w1 = ((const float4*)wmax[p])[1];
        float m_next = fmaxf(fmaxf(fmaxf(w0.x, w0.y), fmaxf(w0.z, w0.w)),
                             fmaxf(fmaxf(w1.x, w1.y), fmaxf(w1.z, w1.w)));

        // half-dot: i in [64h, 64h+64)
        const ulonglong2* v2 = (const ulonglong2*)(v[p] + (h << 6));
        unsigned long long a0 = 0ull, a1 = 0ull, a2 = 0ull, a3 = 0ull;
        #pragma unroll
        for (int i = 0; i < 16; i += 2) {
            ulonglong2 x = v2[i];
            ulonglong2 y = v2[i + 1];
            asm("fma.rn.f32x2 %0, %1, %2, %0;" : "+l"(a0) : "l"(E2[2*i    ]), "l"(x.x));
            asm("fma.rn.f32x2 %0, %1, %2, %0;" : "+l"(a1) : "l"(E2[2*i + 1]), "l"(x.y));
            asm("fma.rn.f32x2 %0, %1, %2, %0;" : "+l"(a2) : "l"(E2[2*i + 2]), "l"(y.x));
            asm("fma.rn.f32x2 %0, %1, %2, %0;" : "+l"(a3) : "l"(E2[2*i + 3]), "l"(y.y));
        }
        unsigned long long s01, s23, sall;
        asm("add.rn.f32x2 %0, %1, %2;" : "=l"(s01)  : "l"(a0),  "l"(a1));
        asm("add.rn.f32x2 %0, %1, %2;" : "=l"(s23)  : "l"(a2),  "l"(a3));
        asm("add.rn.f32x2 %0, %1, %2;" : "=l"(sall) : "l"(s01), "l"(s23));
        float plo, phi;
        asm("mov.b64 {%0, %1}, %2;" : "=f"(plo), "=f"(phi) : "l"(sall));
        float s = plo + phi;
        s += __shfl_xor_sync(0xffffffffu, s, 1);       // combine the two halves

        alpha  = lg_cur + m_lag + __logf(s);           // exact reconstruction
        m_lag  = m_next;
        lg_cur = lg_n1;
        lg_n1  = lg_n2;
        p ^= 1;
    }

    // ---- finalize: alpha += trans[end][j]; norm = exact logsumexp ----
    __syncthreads();                                   // protect wmax/sred reuse
    alpha += trans[(L - 1) * L + j];

    float mw = finv(__reduce_max_sync(0xffffffffu, fkey(alpha)));
    if (lane == 0) wmax[0][warp] = mw;
    __syncthreads();
    float4 w0 = ((const float4*)wmax[0])[0];
    float4 w1 = ((const float4*)wmax[0])[1];
    const float mg = fmaxf(fmaxf(fmaxf(w0.x, w0.y), fmaxf(w0.z, w0.w)),
                           fmaxf(fmaxf(w1.x, w1.y), fmaxf(w1.z, w1.w)));

    float e = (h == 0) ? __expf(alpha - mg) : 0.f;     // count each state once
    #pragma unroll
    for (int o = 16; o; o >>= 1) e += __shfl_xor_sync(0xffffffffu, e, o);
    if (lane == 0) sred[warp] = e;
    __syncthreads();

    if (tid == 0) {
        float S = 0.f;
        #pragma unroll
        for (int w = 0; w < 8; ++w) S += sred[w];
        out[b] = gold - (mg + __logf(S));
    }
}

extern "C" void kernel_launch(void* const* d_in, const int* in_sizes, int n_in,
                              void* d_out, int out_size)
{
    const float* logits = (const float*)d_in[0];
    const int*   labels = (const int*)  d_in[1];
    const int*   lens   = (const int*)  d_in[2];
    const float* trans  = (const float*)d_in[3];
    float*       out    = (float*)d_out;

    crf_fwd_kernel<<<BB, THR>>>(logits, labels, lens, trans, out);
}

// round 4
// speedup vs baseline: 1.6951x; 1.6951x over previous
#include <cuda_runtime.h>

#define BB  256
#define TT  1024
#define NUM 126
#define L   128

// monotone float -> uint key (order-preserving), and inverse
__device__ __forceinline__ unsigned fkey(float f) {
    int b = __float_as_int(f);
    return (unsigned)(b >= 0 ? (b ^ 0x80000000) : ~b);
}
__device__ __forceinline__ float finv(unsigned k) {
    int b = (k & 0x80000000u) ? (int)(k ^ 0x80000000u) : ~(int)k;
    return __int_as_float(b);
}

__global__ __launch_bounds__(128) void crf_fwd_kernel(
    const float* __restrict__ logits,     // [B, T, NUM]
    const int*   __restrict__ labels,     // [B, T]
    const int*   __restrict__ lens,       // [B]
    const float* __restrict__ trans,      // [L, L]
    float*       __restrict__ out)        // [B]
{
    const int b    = blockIdx.x;
    const int j    = threadIdx.x;        // one thread per state
    const int warp = j >> 5;
    const int lane = j & 31;
    const int len  = lens[b];

    __shared__ __align__(16) float v[2][L];
    __shared__ __align__(16) float wmax[2][4];
    __shared__ float sred[4];

    // ---- E2[i] = packed f32x2 { exp(trans[j][2i]), exp(trans[j][2i+1]) } ----
    unsigned long long E2[L / 2];
    #pragma unroll
    for (int i = 0; i < L / 2; ++i) {
        float lo = __expf(trans[j * L + 2 * i]);
        float hi = __expf(trans[j * L + 2 * i + 1]);
        asm("mov.b64 %0, {%1, %2};" : "=l"(E2[i]) : "f"(lo), "f"(hi));
    }

    // ---- gold score (cooperative over time) ----
    const int*   lab_b = labels + b * TT;
    const float* log_b = logits + (size_t)b * TT * NUM;

    float g = 0.f;
    for (int t = j; t < len; t += L) {
        int lab = lab_b[t];
        g += log_b[(size_t)t * NUM + lab];               // unary
        if (t > 0) g += trans[lab * L + lab_b[t - 1]];   // binary
    }
    if (j == 0) {
        g += trans[lab_b[0] * L + (L - 2)];              // start -> labels[0]
        g += trans[(L - 1) * L + lab_b[len - 1]];        // labels[len-1] -> end
    }
    #pragma unroll
    for (int o = 16; o; o >>= 1) g += __shfl_xor_sync(0xffffffffu, g, o);
    if (lane == 0) sred[warp] = g;
    __syncthreads();
    const float gold = sred[0] + sred[1] + sred[2] + sred[3];

    // ---- forward recursion ----
    // Invariants entering iteration t (after the barrier):
    //   v[p]      = v_{t-1} = exp(alpha_{t-1} - m_used_{t-1})   (s*u form)
    //   wmax[p]   = per-warp maxes of alpha_{t-2}  (lag-2 shift source)
    //   s_prev    = s_{t-1}, base_prev = lg_{t-1} + m_used_{t-2}
    //   so alpha_{t-1} = base_prev + log(s_prev)   (computed off-path here)
    const float alpha0 = (j == L - 2) ? 0.f : -100.f;
    v[0][j] = __expf(alpha0);                 // shift 0 (max alpha0 = 0)
    if (j < 4) wmax[0][j] = 0.f;              // m for step 0 := 0
    float s_prev    = 1.f;                    // log(1)=0 -> alpha_{-1} = alpha0
    float base_prev = alpha0;
    float m_used    = 0.f;                    // shift of v[0]

    float lg_cur = (j < NUM) ? log_b[j] : -1000.f;
    float lg_n1  = (j < NUM && 1 < len) ? log_b[NUM + j] : -1000.f;

    int p = 0;
    for (int t = 0; t < len; ++t) {
        __syncthreads();                      // ONE barrier / step (top)

        // ---- off-critical-path chain: previous alpha -> lagged max ----
        float alpha_prev = base_prev + __logf(s_prev);
        float mw = finv(__reduce_max_sync(0xffffffffu, fkey(alpha_prev)));
        if (lane == 0) wmax[p ^ 1][warp] = mw;

        // prefetch 2 steps ahead
        float lg_n2 = -1000.f;
        if (j < NUM && t + 2 < len)
            lg_n2 = log_b[(size_t)(t + 2) * NUM + j];

        // ---- shift for this step (lag-2 max), u-factor (off dot path) ----
        float4 w4 = *(const float4*)wmax[p];
        float m_cur = fmaxf(fmaxf(w4.x, w4.y), fmaxf(w4.z, w4.w));
        float u = __expf(lg_cur + m_used - m_cur);

        // ---- critical path: s = dot(E[j][:], v_{t-1}) ----
        const ulonglong2* v2 = (const ulonglong2*)v[p];
        unsigned long long a0 = 0ull, a1 = 0ull, a2 = 0ull, a3 = 0ull;
        #pragma unroll
        for (int i = 0; i < 16; ++i) {
            ulonglong2 x = v2[2 * i];
            ulonglong2 y = v2[2 * i + 1];
            asm("fma.rn.f32x2 %0, %1, %2, %0;" : "+l"(a0) : "l"(E2[4*i    ]), "l"(x.x));
            asm("fma.rn.f32x2 %0, %1, %2, %0;" : "+l"(a1) : "l"(E2[4*i + 1]), "l"(x.y));
            asm("fma.rn.f32x2 %0, %1, %2, %0;" : "+l"(a2) : "l"(E2[4*i + 2]), "l"(y.x));
            asm("fma.rn.f32x2 %0, %1, %2, %0;" : "+l"(a3) : "l"(E2[4*i + 3]), "l"(y.y));
        }
        unsigned long long s01, s23, sall;
        asm("add.rn.f32x2 %0, %1, %2;" : "=l"(s01)  : "l"(a0),  "l"(a1));
        asm("add.rn.f32x2 %0, %1, %2;" : "=l"(s23)  : "l"(a2),  "l"(a3));
        asm("add.rn.f32x2 %0, %1, %2;" : "=l"(sall) : "l"(s01), "l"(s23));
        float plo, phi;
        asm("mov.b64 {%0, %1}, %2;" : "=f"(plo), "=f"(phi) : "l"(sall));
        float s = plo + phi;

        v[p ^ 1][j] = s * u;                  // v_t, no exp/log on this path

        // roll state (all off-path)
        base_prev = lg_cur + m_used;          // alpha_t = base_prev + log(s)
        s_prev    = s;
        m_used    = m_cur;
        lg_cur    = lg_n1;
        lg_n1     = lg_n2;
        p ^= 1;
    }

    // ---- finalize: alpha_len, add end transitions, exact logsumexp ----
    __syncthreads();                          // loop smem no longer in flight
    float alpha = base_prev + __logf(s_prev);
    alpha += trans[(L - 1) * L + j];

    float mw = finv(__reduce_max_sync(0xffffffffu, fkey(alpha)));
    if (lane == 0) wmax[0][warp] = mw;
    __syncthreads();
    float4 w4 = *(const float4*)wmax[0];
    const float mg = fmaxf(fmaxf(w4.x, w4.y), fmaxf(w4.z, w4.w));

    float e = __expf(alpha - mg);
    #pragma unroll
    for (int o = 16; o; o >>= 1) e += __shfl_xor_sync(0xffffffffu, e, o);
    if (lane == 0) sred[warp] = e;
    __syncthreads();

    if (j == 0) {
        float S = sred[0] + sred[1] + sred[2] + sred[3];
        out[b] = gold - (mg + __logf(S));
    }
}

extern "C" void kernel_launch(void* const* d_in, const int* in_sizes, int n_in,
                              void* d_out, int out_size)
{
    const float* logits = (const float*)d_in[0];
    const int*   labels = (const int*)  d_in[1];
    const int*   lens   = (const int*)  d_in[2];
    const float* trans  = (const float*)d_in[3];
    float*       out    = (float*)d_out;

    crf_fwd_kernel<<<BB, L>>>(logits, labels, lens, trans, out);
}